// round 2
// baseline (speedup 1.0000x reference)
#include <cuda_runtime.h>
#include <cuda_bf16.h>
#include <math.h>
#include <stdint.h>

// Problem constants
#define B_ 256
#define T_ 2048
#define C_ 12
#define K_ 4
#define L_ 8
#define FEAT_ 64
#define HID_ 128
#define NCLS_ 10
#define N2_ 1024
#define TR_ 1025
#define EPS_ 1e-5f
#define NBP_ 32   // partial blocks per channel for BN stats

// ---------------------------------------------------------------------------
// Device scratch (static; no runtime allocation)
// ---------------------------------------------------------------------------
__device__ float g_filt[K_ * TR_];                               // UVMD filters
__device__ float d_modes[(size_t)K_ * B_ * C_ * T_];             // 96 MB
__device__ float d_h1[(size_t)K_ * B_ * 32 * T_];                // 256 MB
__device__ float d_h2[(size_t)K_ * B_ * 64 * T_];                // 512 MB
__device__ float d_h3[(size_t)K_ * B_ * 64 * T_];                // 512 MB
__device__ float d_psum[K_ * 64 * NBP_];
__device__ float d_psq[K_ * 64 * NBP_];
__device__ float d_mean[K_ * 64];
__device__ float d_rstd[K_ * 64];
__device__ float d_feats[B_ * K_ * FEAT_];

// ---------------------------------------------------------------------------
// 1. Compute UVMD frequency-domain filters g_k(f).
//    The scan is linear in f_hat with real coefficients, so run it once with
//    f_hat = 1 per frequency bin.
// ---------------------------------------------------------------------------
__device__ __forceinline__ float softplusf(float x) {
    if (x > 20.f) return x;
    return log1pf(expf(x));
}

__global__ __launch_bounds__(128) void g_kernel(
        const float* __restrict__ log_alpha,
        const float* __restrict__ raw_tau,
        const float* __restrict__ raw_omega) {
    float om[K_];
#pragma unroll
    for (int k = 0; k < K_; k++) om[k] = 0.5f / (1.0f + expf(-raw_omega[k]));
    int f = blockIdx.x * blockDim.x + threadIdx.x;
    if (f >= TR_) return;
    float fr = 0.5f * (float)f / 1024.0f;
    float u[K_] = {0.f, 0.f, 0.f, 0.f};
    float lam = 0.f;
    for (int l = 0; l < L_; l++) {
        float tau_l = softplusf(raw_tau[l]);
        float us = u[0] + u[1] + u[2] + u[3];
        float nu[K_], ns = 0.f;
#pragma unroll
        for (int k = 0; k < K_; k++) {
            float a = expf(log_alpha[l * K_ + k]);
            float d = fr - om[k];
            float num = 1.0f - (us - u[k]) + 0.5f * lam;
            nu[k] = num / (1.0f + 2.0f * a * d * d);
            ns += nu[k];
        }
#pragma unroll
        for (int k = 0; k < K_; k++) u[k] = nu[k];
        lam += tau_l * (1.0f - ns);
    }
#pragma unroll
    for (int k = 0; k < K_; k++) g_filt[k * TR_ + f] = u[k];
}

// ---------------------------------------------------------------------------
// 2. Fused rfft -> filter -> irfft (per signal), writes modes (K,B,C,T).
//    1024-point complex FFT with even/odd real packing.
// ---------------------------------------------------------------------------
__device__ __forceinline__ void fft1024(float* zr, float* zi,
                                        const float* twr, const float* twi,
                                        float dir, int tid) {
#pragma unroll
    for (int s = 0; s < 10; s++) {
        int half = 1 << s;
        int shift = 9 - s;
#pragma unroll
        for (int rep = 0; rep < 2; rep++) {
            int i = tid + rep * 256;
            int pos = i & (half - 1);
            int blk = i >> s;
            int i1 = (blk << (s + 1)) + pos;
            int i2 = i1 + half;
            int ti = pos << shift;
            float c = twr[ti];
            float sn = dir * twi[ti];
            float x2r = zr[i2], x2i = zi[i2];
            float tr = c * x2r - sn * x2i;
            float tim = sn * x2r + c * x2i;
            float x1r = zr[i1], x1i = zi[i1];
            zr[i2] = x1r - tr; zi[i2] = x1i - tim;
            zr[i1] = x1r + tr; zi[i1] = x1i + tim;
        }
        __syncthreads();
    }
}

__global__ __launch_bounds__(256) void uvmd_kernel(const float* __restrict__ x) {
    __shared__ float twr[512], twi[512];
    __shared__ float zr[N2_], zi[N2_];
    __shared__ float Xr[TR_], Xi[TR_];
    int tid = threadIdx.x;
    int sig = blockIdx.x;
    int b = sig / C_, c = sig % C_;

    for (int j = tid; j < 512; j += 256) {
        float ang = (float)M_PI * (float)j / 512.0f;
        twr[j] = cosf(ang);
        twi[j] = -sinf(ang);   // forward twiddle sign
    }
    const float* xb = x + (size_t)b * T_ * C_ + c;
    for (int n = tid; n < N2_; n += 256) {
        int j = __brev((unsigned)n) >> 22;
        zr[n] = xb[(size_t)(2 * j) * C_];
        zi[n] = xb[(size_t)(2 * j + 1) * C_];
    }
    __syncthreads();
    fft1024(zr, zi, twr, twi, 1.0f, tid);   // forward

    // Hermitian unpack: X[0..1024]
    for (int k = tid; k < N2_; k += 256) {
        if (k == 0) {
            Xr[0] = zr[0] + zi[0];   Xi[0] = 0.f;
            Xr[N2_] = zr[0] - zi[0]; Xi[N2_] = 0.f;
        } else {
            float ar = zr[k], ai = zi[k];
            float br = zr[N2_ - k], bi = -zi[N2_ - k];
            float er = 0.5f * (ar + br), ei = 0.5f * (ai + bi);
            float dr = 0.5f * (ar - br), di = 0.5f * (ai - bi);
            float or_ = di, oi = -dr;               // (d)/(i)
            float s_, c_;
            __sincosf(-(float)M_PI * (float)k / 1024.0f, &s_, &c_);
            Xr[k] = er + c_ * or_ - s_ * oi;
            Xi[k] = ei + s_ * or_ + c_ * oi;
        }
    }
    __syncthreads();

    const float invn = 1.0f / 1024.0f;
    for (int km = 0; km < K_; km++) {
        const float* g = g_filt + km * TR_;
        // pack filtered spectrum into bit-reversed order for inverse FFT
        for (int n = tid; n < N2_; n += 256) {
            int k = __brev((unsigned)n) >> 22;
            float vr, vi;
            if (k == 0) {
                float y0 = g[0] * Xr[0];
                float y1 = g[N2_] * Xr[N2_];
                vr = 0.5f * (y0 + y1);
                vi = 0.5f * (y0 - y1);
            } else {
                float gk = g[k], gm = g[N2_ - k];
                float yr = gk * Xr[k], yi = gk * Xi[k];
                float mr = gm * Xr[N2_ - k], mi = -(gm * Xi[N2_ - k]);
                float er = 0.5f * (yr + mr), ei = 0.5f * (yi + mi);
                float dr = 0.5f * (yr - mr), di = 0.5f * (yi - mi);
                float s_, c_;
                __sincosf((float)M_PI * (float)k / 1024.0f, &s_, &c_);
                float or_ = c_ * dr - s_ * di;
                float oi  = s_ * dr + c_ * di;
                vr = er - oi;
                vi = ei + or_;
            }
            zr[n] = vr; zi[n] = vi;
        }
        __syncthreads();
        fft1024(zr, zi, twr, twi, -1.0f, tid);   // inverse (conj twiddles)
        float* orow = d_modes + ((((size_t)km * B_ + b) * C_ + c)) * T_;
        for (int n = tid; n < N2_; n += 256) {
            float2 v = make_float2(zr[n] * invn, zi[n] * invn);
            *reinterpret_cast<float2*>(orow + 2 * n) = v;
        }
        __syncthreads();
    }
}

// ---------------------------------------------------------------------------
// 3. Conv1d (+ fused BN+ReLU of the INPUT stage, applied on smem load)
//    gridDim = (T/TILE, B, K). blockDim = COUT*G = 256.
//    Each thread: one output channel x TT consecutive t positions.
// ---------------------------------------------------------------------------
template <int CIN, int COUT, int KS, int G, int TT>
__global__ __launch_bounds__(256) void conv_kernel(
    const float* __restrict__ in, const float* __restrict__ wgt,
    const float* __restrict__ bias,
    const float* __restrict__ bng, const float* __restrict__ bnb,
    const float* __restrict__ mean, const float* __restrict__ rstd,
    float* __restrict__ out, int apply_bn)
{
    constexpr int TILE = G * TT;
    constexpr int PAD = KS / 2;
    constexpr int IW = TILE + KS - 1;
    __shared__ float s_in[CIN][IW];
    __shared__ float s_a[CIN], s_c[CIN];

    int tx = threadIdx.x;
    int b = blockIdx.y;
    int km = blockIdx.z;
    int t0 = blockIdx.x * TILE;
    const float* inb = in + (((size_t)km * B_ + b) * CIN) * T_;

    if (apply_bn) {
        for (int ci = tx; ci < CIN; ci += 256) {
            float a = bng[km * CIN + ci] * rstd[km * 64 + ci];
            s_a[ci] = a;
            s_c[ci] = bnb[km * CIN + ci] - a * mean[km * 64 + ci];
        }
        __syncthreads();
    }
    for (int idx = tx; idx < CIN * IW; idx += 256) {
        int ci = idx / IW, tl = idx % IW;
        int t = t0 + tl - PAD;
        float v = 0.f;
        if (t >= 0 && t < T_) {
            v = inb[(size_t)ci * T_ + t];
            if (apply_bn) v = fmaxf(fmaf(s_a[ci], v, s_c[ci]), 0.f);
        }
        s_in[ci][tl] = v;
    }
    __syncthreads();

    int co = tx / G;
    int tb = (tx % G) * TT;
    const float* wr = wgt + ((size_t)km * COUT + co) * CIN * KS;
    float bsv = bias[km * COUT + co];
    float acc[TT];
#pragma unroll
    for (int j = 0; j < TT; j++) acc[j] = bsv;

    for (int ci = 0; ci < CIN; ci++) {
        float xv[TT + KS - 1];
#pragma unroll
        for (int j = 0; j < TT + KS - 1; j++) xv[j] = s_in[ci][tb + j];
#pragma unroll
        for (int dk = 0; dk < KS; dk++) {
            float wv = __ldg(&wr[ci * KS + dk]);
#pragma unroll
            for (int j = 0; j < TT; j++) acc[j] = fmaf(wv, xv[j + dk], acc[j]);
        }
    }
    float* op = out + (((size_t)km * B_ + b) * COUT + co) * T_ + t0 + tb;
#pragma unroll
    for (int j = 0; j < TT; j++) op[j] = acc[j];
}

// ---------------------------------------------------------------------------
// 4. BN statistics: two-stage deterministic reduction (no atomics)
// ---------------------------------------------------------------------------
__global__ __launch_bounds__(256) void stats_part_kernel(
    const float* __restrict__ h, int Cout) {
    int ch = blockIdx.x, part = blockIdx.y, km = blockIdx.z;
    int tid = threadIdx.x;
    const float* base = h + ((size_t)km * B_) * Cout * T_;
    float s = 0.f, s2 = 0.f;
    int b0 = part * (B_ / NBP_);
    for (int bb = b0; bb < b0 + (B_ / NBP_); bb++) {
        const float* row = base + ((size_t)bb * Cout + ch) * T_;
        for (int t = tid; t < T_; t += 256) {
            float v = row[t];
            s += v;
            s2 += v * v;
        }
    }
    __shared__ float r1[256], r2[256];
    r1[tid] = s; r2[tid] = s2;
    __syncthreads();
    for (int o = 128; o > 0; o >>= 1) {
        if (tid < o) { r1[tid] += r1[tid + o]; r2[tid] += r2[tid + o]; }
        __syncthreads();
    }
    if (tid == 0) {
        int idx = (km * 64 + ch) * NBP_ + part;
        d_psum[idx] = r1[0];
        d_psq[idx] = r2[0];
    }
}

__global__ __launch_bounds__(64) void stats_fin_kernel(int Cout) {
    int km = blockIdx.x;
    int ch = threadIdx.x;
    if (ch >= Cout) return;
    float s = 0.f, s2 = 0.f;
    for (int p = 0; p < NBP_; p++) {
        s += d_psum[(km * 64 + ch) * NBP_ + p];
        s2 += d_psq[(km * 64 + ch) * NBP_ + p];
    }
    float cnt = (float)B_ * (float)T_;
    float m = s / cnt;
    float v = s2 / cnt - m * m;
    d_mean[km * 64 + ch] = m;
    d_rstd[km * 64 + ch] = rsqrtf(v + EPS_);
}

// ---------------------------------------------------------------------------
// 5. BN+ReLU + mean-pool over T -> feats (B, K*FEAT)
// ---------------------------------------------------------------------------
__global__ __launch_bounds__(256) void pool_kernel(
    const float* __restrict__ h,
    const float* __restrict__ bng, const float* __restrict__ bnb) {
    int co = blockIdx.x, b = blockIdx.y, km = blockIdx.z;
    int tid = threadIdx.x;
    float a = bng[km * FEAT_ + co] * d_rstd[km * 64 + co];
    float cc = bnb[km * FEAT_ + co] - a * d_mean[km * 64 + co];
    const float* row = h + (((size_t)km * B_ + b) * FEAT_ + co) * T_;
    float s = 0.f;
    for (int t = tid; t < T_; t += 256)
        s += fmaxf(fmaf(a, row[t], cc), 0.f);
    __shared__ float r[256];
    r[tid] = s;
    __syncthreads();
    for (int o = 128; o > 0; o >>= 1) {
        if (tid < o) r[tid] += r[tid + o];
        __syncthreads();
    }
    if (tid == 0)
        d_feats[(size_t)b * (K_ * FEAT_) + km * FEAT_ + co] = r[0] * (1.0f / T_);
}

// ---------------------------------------------------------------------------
// 6. Classifier: relu(fused @ fc1^T + b1) @ fc2^T + b2
// ---------------------------------------------------------------------------
__global__ __launch_bounds__(128) void classifier_kernel(
    const float* __restrict__ w1, const float* __restrict__ b1,
    const float* __restrict__ w2, const float* __restrict__ b2,
    float* __restrict__ out) {
    int b = blockIdx.x;
    int j = threadIdx.x;
    __shared__ float sf[K_ * FEAT_];
    __shared__ float sh[HID_];
    for (int i = j; i < K_ * FEAT_; i += 128) sf[i] = d_feats[(size_t)b * (K_ * FEAT_) + i];
    __syncthreads();
    float a = b1[j];
    const float* wr = w1 + (size_t)j * (K_ * FEAT_);
#pragma unroll 8
    for (int i = 0; i < K_ * FEAT_; i++) a = fmaf(sf[i], wr[i], a);
    sh[j] = fmaxf(a, 0.f);
    __syncthreads();
    if (j < NCLS_) {
        float o = b2[j];
        const float* w2r = w2 + (size_t)j * HID_;
#pragma unroll 8
        for (int i = 0; i < HID_; i++) o = fmaf(sh[i], w2r[i], o);
        out[b * NCLS_ + j] = o;
    }
}

// ---------------------------------------------------------------------------
// Launch
// ---------------------------------------------------------------------------
extern "C" void kernel_launch(void* const* d_in, const int* in_sizes, int n_in,
                              void* d_out, int out_size) {
    const float* x         = (const float*)d_in[0];
    const float* log_alpha = (const float*)d_in[1];
    const float* raw_tau   = (const float*)d_in[2];
    const float* raw_omega = (const float*)d_in[3];
    const float* conv_w1   = (const float*)d_in[4];
    const float* conv_b1   = (const float*)d_in[5];
    const float* bn_g1     = (const float*)d_in[6];
    const float* bn_b1     = (const float*)d_in[7];
    const float* conv_w2   = (const float*)d_in[8];
    const float* conv_b2   = (const float*)d_in[9];
    const float* bn_g2     = (const float*)d_in[10];
    const float* bn_b2     = (const float*)d_in[11];
    const float* conv_w3   = (const float*)d_in[12];
    const float* conv_b3   = (const float*)d_in[13];
    const float* bn_g3     = (const float*)d_in[14];
    const float* bn_b3     = (const float*)d_in[15];
    const float* fc1_w     = (const float*)d_in[16];
    const float* fc1_b     = (const float*)d_in[17];
    const float* fc2_w     = (const float*)d_in[18];
    const float* fc2_b     = (const float*)d_in[19];
    float* out = (float*)d_out;

    float *p_modes, *p_h1, *p_h2, *p_h3, *p_mean, *p_rstd;
    cudaGetSymbolAddress((void**)&p_modes, d_modes);
    cudaGetSymbolAddress((void**)&p_h1, d_h1);
    cudaGetSymbolAddress((void**)&p_h2, d_h2);
    cudaGetSymbolAddress((void**)&p_h3, d_h3);
    cudaGetSymbolAddress((void**)&p_mean, d_mean);
    cudaGetSymbolAddress((void**)&p_rstd, d_rstd);

    // 1. UVMD filters
    g_kernel<<<(TR_ + 127) / 128, 128>>>(log_alpha, raw_tau, raw_omega);
    // 2. FFT -> filter -> iFFT -> modes
    uvmd_kernel<<<B_ * C_, 256>>>(x);

    dim3 cgrid(T_ / 64, B_, K_);
    // conv1: 12 -> 32, k=7 (no input BN)
    conv_kernel<12, 32, 7, 8, 8><<<cgrid, 256>>>(
        p_modes, conv_w1, conv_b1, nullptr, nullptr, nullptr, nullptr, p_h1, 0);
    stats_part_kernel<<<dim3(32, NBP_, K_), 256>>>(p_h1, 32);
    stats_fin_kernel<<<K_, 64>>>(32);
    // conv2: 32 -> 64, k=5 (input = BN1+ReLU of h1)
    conv_kernel<32, 64, 5, 4, 16><<<cgrid, 256>>>(
        p_h1, conv_w2, conv_b2, bn_g1, bn_b1, p_mean, p_rstd, p_h2, 1);
    stats_part_kernel<<<dim3(64, NBP_, K_), 256>>>(p_h2, 64);
    stats_fin_kernel<<<K_, 64>>>(64);
    // conv3: 64 -> 64, k=3 (input = BN2+ReLU of h2)
    conv_kernel<64, 64, 3, 4, 16><<<cgrid, 256>>>(
        p_h2, conv_w3, conv_b3, bn_g2, bn_b2, p_mean, p_rstd, p_h3, 1);
    stats_part_kernel<<<dim3(64, NBP_, K_), 256>>>(p_h3, 64);
    stats_fin_kernel<<<K_, 64>>>(64);
    // BN3+ReLU + mean pool
    pool_kernel<<<dim3(FEAT_, B_, K_), 256>>>(p_h3, bn_g3, bn_b3);
    // classifier
    classifier_kernel<<<B_, HID_>>>(fc1_w, fc1_b, fc2_w, fc2_b, out);
}

// round 3
// speedup vs baseline: 1.0704x; 1.0704x over previous
#include <cuda_runtime.h>
#include <cuda_bf16.h>
#include <math.h>
#include <stdint.h>

// Problem constants
#define B_ 256
#define T_ 2048
#define C_ 12
#define K_ 4
#define L_ 8
#define FEAT_ 64
#define HID_ 128
#define NCLS_ 10
#define N2_ 1024
#define TR_ 1025
#define EPS_ 1e-5f
#define NBLK_ 32   // T tiles per signal (TILE=64)

typedef unsigned long long ull;

// ---------------------------------------------------------------------------
// Device scratch (static; no runtime allocation)
// ---------------------------------------------------------------------------
__device__ float g_filt[K_ * TR_];                               // UVMD filters
__device__ float d_modes[(size_t)K_ * B_ * C_ * T_];             // 96 MB
__device__ float d_h1[(size_t)K_ * B_ * 32 * T_];                // 256 MB
__device__ float d_h2[(size_t)K_ * B_ * 64 * T_];                // 512 MB
__device__ float d_h3[(size_t)K_ * B_ * 64 * T_];                // 512 MB
__device__ float d_psum[(size_t)K_ * 64 * B_ * NBLK_];           // 8 MB
__device__ float d_psq[(size_t)K_ * 64 * B_ * NBLK_];            // 8 MB
__device__ float d_mean[K_ * 64];
__device__ float d_rstd[K_ * 64];
__device__ float d_feats[B_ * K_ * FEAT_];

// ---------------------------------------------------------------------------
// Packed f32x2 helpers (Blackwell full-rate fp32 path; ptxas never auto-fuses)
// ---------------------------------------------------------------------------
__device__ __forceinline__ ull pack2(float lo, float hi) {
    ull r; asm("mov.b64 %0, {%1, %2};" : "=l"(r) : "f"(lo), "f"(hi)); return r;
}
__device__ __forceinline__ ull f2u(float2 v) {
    ull r; asm("mov.b64 %0, {%1, %2};" : "=l"(r) : "f"(v.x), "f"(v.y)); return r;
}
__device__ __forceinline__ float2 u2f(ull v) {
    float2 f; asm("mov.b64 {%0, %1}, %2;" : "=f"(f.x), "=f"(f.y) : "l"(v)); return f;
}
__device__ __forceinline__ ull fma2(ull a, ull b, ull c) {
    ull d; asm("fma.rn.f32x2 %0, %1, %2, %3;" : "=l"(d) : "l"(a), "l"(b), "l"(c)); return d;
}
__device__ __forceinline__ ull add2(ull a, ull b) {
    ull d; asm("add.rn.f32x2 %0, %1, %2;" : "=l"(d) : "l"(a), "l"(b)); return d;
}

// ---------------------------------------------------------------------------
// 1. UVMD frequency-domain filters g_k(f): the scan is linear in f_hat with
//    real coefficients, so run it once with f_hat = 1 per bin.
// ---------------------------------------------------------------------------
__device__ __forceinline__ float softplusf(float x) {
    if (x > 20.f) return x;
    return log1pf(expf(x));
}

__global__ __launch_bounds__(128) void g_kernel(
        const float* __restrict__ log_alpha,
        const float* __restrict__ raw_tau,
        const float* __restrict__ raw_omega) {
    float om[K_];
#pragma unroll
    for (int k = 0; k < K_; k++) om[k] = 0.5f / (1.0f + expf(-raw_omega[k]));
    int f = blockIdx.x * blockDim.x + threadIdx.x;
    if (f >= TR_) return;
    float fr = 0.5f * (float)f / 1024.0f;
    float u[K_] = {0.f, 0.f, 0.f, 0.f};
    float lam = 0.f;
    for (int l = 0; l < L_; l++) {
        float tau_l = softplusf(raw_tau[l]);
        float us = u[0] + u[1] + u[2] + u[3];
        float nu[K_], ns = 0.f;
#pragma unroll
        for (int k = 0; k < K_; k++) {
            float a = expf(log_alpha[l * K_ + k]);
            float d = fr - om[k];
            float num = 1.0f - (us - u[k]) + 0.5f * lam;
            nu[k] = num / (1.0f + 2.0f * a * d * d);
            ns += nu[k];
        }
#pragma unroll
        for (int k = 0; k < K_; k++) u[k] = nu[k];
        lam += tau_l * (1.0f - ns);
    }
#pragma unroll
    for (int k = 0; k < K_; k++) g_filt[k * TR_ + f] = u[k];
}

// ---------------------------------------------------------------------------
// 2. Fused rfft -> filter -> irfft per (b,c) signal; writes modes (K,B,C,T).
// ---------------------------------------------------------------------------
__device__ __forceinline__ void fft1024(float* zr, float* zi,
                                        const float* twr, const float* twi,
                                        float dir, int tid) {
#pragma unroll
    for (int s = 0; s < 10; s++) {
        int half = 1 << s;
        int shift = 9 - s;
#pragma unroll
        for (int rep = 0; rep < 2; rep++) {
            int i = tid + rep * 256;
            int pos = i & (half - 1);
            int blk = i >> s;
            int i1 = (blk << (s + 1)) + pos;
            int i2 = i1 + half;
            int ti = pos << shift;
            float c = twr[ti];
            float sn = dir * twi[ti];
            float x2r = zr[i2], x2i = zi[i2];
            float tr = c * x2r - sn * x2i;
            float tim = sn * x2r + c * x2i;
            float x1r = zr[i1], x1i = zi[i1];
            zr[i2] = x1r - tr; zi[i2] = x1i - tim;
            zr[i1] = x1r + tr; zi[i1] = x1i + tim;
        }
        __syncthreads();
    }
}

__global__ __launch_bounds__(256) void uvmd_kernel(const float* __restrict__ x) {
    __shared__ float twr[512], twi[512];
    __shared__ float zr[N2_], zi[N2_];
    __shared__ float Xr[TR_], Xi[TR_];
    int tid = threadIdx.x;
    int sig = blockIdx.x;
    int b = sig / C_, c = sig % C_;

    for (int j = tid; j < 512; j += 256) {
        float ang = (float)M_PI * (float)j / 512.0f;
        twr[j] = cosf(ang);
        twi[j] = -sinf(ang);
    }
    const float* xb = x + (size_t)b * T_ * C_ + c;
    for (int n = tid; n < N2_; n += 256) {
        int j = __brev((unsigned)n) >> 22;
        zr[n] = xb[(size_t)(2 * j) * C_];
        zi[n] = xb[(size_t)(2 * j + 1) * C_];
    }
    __syncthreads();
    fft1024(zr, zi, twr, twi, 1.0f, tid);

    for (int k = tid; k < N2_; k += 256) {
        if (k == 0) {
            Xr[0] = zr[0] + zi[0];   Xi[0] = 0.f;
            Xr[N2_] = zr[0] - zi[0]; Xi[N2_] = 0.f;
        } else {
            float ar = zr[k], ai = zi[k];
            float br = zr[N2_ - k], bi = -zi[N2_ - k];
            float er = 0.5f * (ar + br), ei = 0.5f * (ai + bi);
            float dr = 0.5f * (ar - br), di = 0.5f * (ai - bi);
            float or_ = di, oi = -dr;
            float s_, c_;
            __sincosf(-(float)M_PI * (float)k / 1024.0f, &s_, &c_);
            Xr[k] = er + c_ * or_ - s_ * oi;
            Xi[k] = ei + s_ * or_ + c_ * oi;
        }
    }
    __syncthreads();

    const float invn = 1.0f / 1024.0f;
    for (int km = 0; km < K_; km++) {
        const float* g = g_filt + km * TR_;
        for (int n = tid; n < N2_; n += 256) {
            int k = __brev((unsigned)n) >> 22;
            float vr, vi;
            if (k == 0) {
                float y0 = g[0] * Xr[0];
                float y1 = g[N2_] * Xr[N2_];
                vr = 0.5f * (y0 + y1);
                vi = 0.5f * (y0 - y1);
            } else {
                float gk = g[k], gm = g[N2_ - k];
                float yr = gk * Xr[k], yi = gk * Xi[k];
                float mr = gm * Xr[N2_ - k], mi = -(gm * Xi[N2_ - k]);
                float er = 0.5f * (yr + mr), ei = 0.5f * (yi + mi);
                float dr = 0.5f * (yr - mr), di = 0.5f * (yi - mi);
                float s_, c_;
                __sincosf((float)M_PI * (float)k / 1024.0f, &s_, &c_);
                float or_ = c_ * dr - s_ * di;
                float oi  = s_ * dr + c_ * di;
                vr = er - oi;
                vi = ei + or_;
            }
            zr[n] = vr; zi[n] = vi;
        }
        __syncthreads();
        fft1024(zr, zi, twr, twi, -1.0f, tid);
        float* orow = d_modes + ((((size_t)km * B_ + b) * C_ + c)) * T_;
        for (int n = tid; n < N2_; n += 256) {
            float2 v = make_float2(zr[n] * invn, zi[n] * invn);
            *reinterpret_cast<float2*>(orow + 2 * n) = v;
        }
        __syncthreads();
    }
}

// ---------------------------------------------------------------------------
// 3. Conv1d with packed f32x2 math, fused input BN+ReLU (previous stage),
//    fused BN-stat partials of this stage's output.
//    gridDim = (T/TILE, B, K). blockDim = COUT*G = 256.
//    Each thread: one output channel x TT consecutive t (as TT/2 f32x2 pairs).
// ---------------------------------------------------------------------------
template <int CIN, int COUT, int KS, int G, int TT>
__global__ __launch_bounds__(256) void conv_kernel(
    const float* __restrict__ in, const float* __restrict__ wgt,
    const float* __restrict__ bias,
    const float* __restrict__ bng, const float* __restrict__ bnb,
    const float* __restrict__ mean, const float* __restrict__ rstd,
    float* __restrict__ out, float* __restrict__ psum, float* __restrict__ psq,
    int apply_bn)
{
    constexpr int TILE = G * TT;
    constexpr int PAD = KS / 2;
    constexpr int IW = TILE + KS - 1;
    constexpr int NEV = (TT + KS) / 2;            // float2 pairs loaded per ci
    constexpr int NODD = TT / 2 + (KS - 3) / 2;   // odd-aligned pairs per ci
    __shared__ float s_in[CIN][IW];
    __shared__ float s_a[CIN], s_c[CIN];

    int tx = threadIdx.x;
    int b = blockIdx.y;
    int km = blockIdx.z;
    int t0 = blockIdx.x * TILE;
    const float* inb = in + (((size_t)km * B_ + b) * CIN) * T_;

    if (apply_bn) {
        for (int ci = tx; ci < CIN; ci += 256) {
            float a = bng[km * CIN + ci] * rstd[km * 64 + ci];
            s_a[ci] = a;
            s_c[ci] = bnb[km * CIN + ci] - a * mean[km * 64 + ci];
        }
        __syncthreads();
    }
    for (int idx = tx; idx < CIN * IW; idx += 256) {
        int ci = idx / IW, tl = idx % IW;
        int t = t0 + tl - PAD;
        float v = 0.f;
        if (t >= 0 && t < T_) {
            v = inb[(size_t)ci * T_ + t];
            if (apply_bn) v = fmaxf(fmaf(s_a[ci], v, s_c[ci]), 0.f);
        }
        s_in[ci][tl] = v;
    }
    __syncthreads();

    int co = tx / G;
    int g = tx % G;
    int tb = g * TT;                   // even; float2-aligned
    const float* wr = wgt + ((size_t)km * COUT + co) * CIN * KS;
    float bsv = bias[km * COUT + co];
    ull acc[TT / 2];
    ull binit = pack2(bsv, bsv);
#pragma unroll
    for (int p = 0; p < TT / 2; p++) acc[p] = binit;

    for (int ci = 0; ci < CIN; ci++) {
        const float2* r2 = reinterpret_cast<const float2*>(&s_in[ci][0]) + (tb >> 1);
        float2 ev[NEV];
#pragma unroll
        for (int i = 0; i < NEV; i++) ev[i] = r2[i];
        ull evu[NEV];
#pragma unroll
        for (int i = 0; i < NEV; i++) evu[i] = f2u(ev[i]);
        ull odd[NODD];
#pragma unroll
        for (int p = 0; p < NODD; p++) odd[p] = pack2(ev[p].y, ev[p + 1].x);
#pragma unroll
        for (int dk = 0; dk < KS; dk++) {
            float wv = __ldg(&wr[ci * KS + dk]);
            ull w2 = pack2(wv, wv);
            if ((dk & 1) == 0) {
                int o = dk >> 1;
#pragma unroll
                for (int p = 0; p < TT / 2; p++) acc[p] = fma2(evu[p + o], w2, acc[p]);
            } else {
                int o = (dk - 1) >> 1;
#pragma unroll
                for (int p = 0; p < TT / 2; p++) acc[p] = fma2(odd[p + o], w2, acc[p]);
            }
        }
    }

    // store outputs (pre-BN) + accumulate stats partials
    float* op = out + (((size_t)km * B_ + b) * COUT + co) * T_ + t0 + tb;
    ull ssum = pack2(0.f, 0.f), qsum = pack2(0.f, 0.f);
#pragma unroll
    for (int p = 0; p < TT / 2; p++) {
        float2 o = u2f(acc[p]);
        *reinterpret_cast<float2*>(op + 2 * p) = o;
        ssum = add2(ssum, acc[p]);
        qsum = fma2(acc[p], acc[p], qsum);
    }
    float2 fs = u2f(ssum), fq = u2f(qsum);
    float s = fs.x + fs.y;
    float q = fq.x + fq.y;
#pragma unroll
    for (int o = G / 2; o > 0; o >>= 1) {
        s += __shfl_down_sync(0xffffffffu, s, o);
        q += __shfl_down_sync(0xffffffffu, q, o);
    }
    if (g == 0) {
        size_t pidx = ((size_t)(km * COUT + co) * B_ + b) * NBLK_ + blockIdx.x;
        psum[pidx] = s;
        psq[pidx] = q;
    }
}

// ---------------------------------------------------------------------------
// 4. BN statistics finalize: one block per (km, ch), sums B*NBLK partials.
// ---------------------------------------------------------------------------
__global__ __launch_bounds__(256) void stats_fin_kernel(int Cout) {
    int co = blockIdx.x, km = blockIdx.y;
    int tid = threadIdx.x;
    const float* ps = d_psum + (size_t)(km * Cout + co) * B_ * NBLK_;
    const float* pq = d_psq + (size_t)(km * Cout + co) * B_ * NBLK_;
    float s = 0.f, q = 0.f;
    for (int i = tid; i < B_ * NBLK_; i += 256) {
        s += ps[i];
        q += pq[i];
    }
    __shared__ float r1[256], r2[256];
    r1[tid] = s; r2[tid] = q;
    __syncthreads();
    for (int o = 128; o > 0; o >>= 1) {
        if (tid < o) { r1[tid] += r1[tid + o]; r2[tid] += r2[tid + o]; }
        __syncthreads();
    }
    if (tid == 0) {
        float cnt = (float)B_ * (float)T_;
        float m = r1[0] / cnt;
        float v = r2[0] / cnt - m * m;
        d_mean[km * 64 + co] = m;
        d_rstd[km * 64 + co] = rsqrtf(v + EPS_);
    }
}

// ---------------------------------------------------------------------------
// 5. BN+ReLU + mean-pool over T -> feats (B, K*FEAT)
// ---------------------------------------------------------------------------
__global__ __launch_bounds__(256) void pool_kernel(
    const float* __restrict__ h,
    const float* __restrict__ bng, const float* __restrict__ bnb) {
    int co = blockIdx.x, b = blockIdx.y, km = blockIdx.z;
    int tid = threadIdx.x;
    float a = bng[km * FEAT_ + co] * d_rstd[km * 64 + co];
    float cc = bnb[km * FEAT_ + co] - a * d_mean[km * 64 + co];
    const float* row = h + (((size_t)km * B_ + b) * FEAT_ + co) * T_;
    float s = 0.f;
    for (int t = tid; t < T_; t += 256)
        s += fmaxf(fmaf(a, row[t], cc), 0.f);
    __shared__ float r[256];
    r[tid] = s;
    __syncthreads();
    for (int o = 128; o > 0; o >>= 1) {
        if (tid < o) r[tid] += r[tid + o];
        __syncthreads();
    }
    if (tid == 0)
        d_feats[(size_t)b * (K_ * FEAT_) + km * FEAT_ + co] = r[0] * (1.0f / T_);
}

// ---------------------------------------------------------------------------
// 6. Classifier: relu(fused @ fc1^T + b1) @ fc2^T + b2
// ---------------------------------------------------------------------------
__global__ __launch_bounds__(128) void classifier_kernel(
    const float* __restrict__ w1, const float* __restrict__ b1,
    const float* __restrict__ w2, const float* __restrict__ b2,
    float* __restrict__ out) {
    int b = blockIdx.x;
    int j = threadIdx.x;
    __shared__ float sf[K_ * FEAT_];
    __shared__ float sh[HID_];
    for (int i = j; i < K_ * FEAT_; i += 128) sf[i] = d_feats[(size_t)b * (K_ * FEAT_) + i];
    __syncthreads();
    float a = b1[j];
    const float* wr = w1 + (size_t)j * (K_ * FEAT_);
#pragma unroll 8
    for (int i = 0; i < K_ * FEAT_; i++) a = fmaf(sf[i], wr[i], a);
    sh[j] = fmaxf(a, 0.f);
    __syncthreads();
    if (j < NCLS_) {
        float o = b2[j];
        const float* w2r = w2 + (size_t)j * HID_;
#pragma unroll 8
        for (int i = 0; i < HID_; i++) o = fmaf(sh[i], w2r[i], o);
        out[b * NCLS_ + j] = o;
    }
}

// ---------------------------------------------------------------------------
// Launch
// ---------------------------------------------------------------------------
extern "C" void kernel_launch(void* const* d_in, const int* in_sizes, int n_in,
                              void* d_out, int out_size) {
    const float* x         = (const float*)d_in[0];
    const float* log_alpha = (const float*)d_in[1];
    const float* raw_tau   = (const float*)d_in[2];
    const float* raw_omega = (const float*)d_in[3];
    const float* conv_w1   = (const float*)d_in[4];
    const float* conv_b1   = (const float*)d_in[5];
    const float* bn_g1     = (const float*)d_in[6];
    const float* bn_b1     = (const float*)d_in[7];
    const float* conv_w2   = (const float*)d_in[8];
    const float* conv_b2   = (const float*)d_in[9];
    const float* bn_g2     = (const float*)d_in[10];
    const float* bn_b2     = (const float*)d_in[11];
    const float* conv_w3   = (const float*)d_in[12];
    const float* conv_b3   = (const float*)d_in[13];
    const float* bn_g3     = (const float*)d_in[14];
    const float* bn_b3     = (const float*)d_in[15];
    const float* fc1_w     = (const float*)d_in[16];
    const float* fc1_b     = (const float*)d_in[17];
    const float* fc2_w     = (const float*)d_in[18];
    const float* fc2_b     = (const float*)d_in[19];
    float* out = (float*)d_out;

    float *p_modes, *p_h1, *p_h2, *p_h3, *p_mean, *p_rstd, *p_psum, *p_psq;
    cudaGetSymbolAddress((void**)&p_modes, d_modes);
    cudaGetSymbolAddress((void**)&p_h1, d_h1);
    cudaGetSymbolAddress((void**)&p_h2, d_h2);
    cudaGetSymbolAddress((void**)&p_h3, d_h3);
    cudaGetSymbolAddress((void**)&p_mean, d_mean);
    cudaGetSymbolAddress((void**)&p_rstd, d_rstd);
    cudaGetSymbolAddress((void**)&p_psum, d_psum);
    cudaGetSymbolAddress((void**)&p_psq, d_psq);

    // 1. UVMD filters
    g_kernel<<<(TR_ + 127) / 128, 128>>>(log_alpha, raw_tau, raw_omega);
    // 2. FFT -> filter -> iFFT -> modes
    uvmd_kernel<<<B_ * C_, 256>>>(x);

    dim3 cgrid(NBLK_, B_, K_);
    // conv1: 12 -> 32, k=7 (no input BN); stats fused
    conv_kernel<12, 32, 7, 8, 8><<<cgrid, 256>>>(
        p_modes, conv_w1, conv_b1, nullptr, nullptr, nullptr, nullptr,
        p_h1, p_psum, p_psq, 0);
    stats_fin_kernel<<<dim3(32, K_), 256>>>(32);
    // conv2: 32 -> 64, k=5 (input = BN1+ReLU of h1); stats fused
    conv_kernel<32, 64, 5, 4, 16><<<cgrid, 256>>>(
        p_h1, conv_w2, conv_b2, bn_g1, bn_b1, p_mean, p_rstd,
        p_h2, p_psum, p_psq, 1);
    stats_fin_kernel<<<dim3(64, K_), 256>>>(64);
    // conv3: 64 -> 64, k=3 (input = BN2+ReLU of h2); stats fused
    conv_kernel<64, 64, 3, 4, 16><<<cgrid, 256>>>(
        p_h2, conv_w3, conv_b3, bn_g2, bn_b2, p_mean, p_rstd,
        p_h3, p_psum, p_psq, 1);
    stats_fin_kernel<<<dim3(64, K_), 256>>>(64);
    // BN3+ReLU + mean pool
    pool_kernel<<<dim3(FEAT_, B_, K_), 256>>>(p_h3, bn_g3, bn_b3);
    // classifier
    classifier_kernel<<<B_, HID_>>>(fc1_w, fc1_b, fc2_w, fc2_b, out);
}